// round 1
// baseline (speedup 1.0000x reference)
#include <cuda_runtime.h>

#define T_STEPS 8192
#define IDIM 256
#define HDIM 1024
#define GDIM 4096          // 4*HDIM
#define NBLOCKS 128
#define NTHREADS 256       // 8 warps; warp w handles h index j = 8*block + w

// h history: row t holds h_{t-1} input for step t; row 0 = zeros. 32 MB + change.
__device__ float g_hs[(T_STEPS + 1) * HDIM];
__device__ unsigned int g_count;

__global__ void init_kernel() {
    int i = threadIdx.x + blockIdx.x * blockDim.x;
    if (i < HDIM) g_hs[i] = 0.0f;
    if (i == 0) g_count = 0u;
}

__device__ __forceinline__ float sigmoidf_fast(float x) {
    return 1.0f / (1.0f + __expf(-x));
}

__global__ void __launch_bounds__(NTHREADS, 1)
lstm_kernel(const float* __restrict__ seq,
            const float* __restrict__ W_ih,
            const float* __restrict__ W_hh,
            const float* __restrict__ b_ih,
            const float* __restrict__ b_hh)
{
    __shared__ float h_s[HDIM];
    __shared__ float x_s[IDIM];

    const int tid  = threadIdx.x;
    const int warp = tid >> 5;
    const int lane = tid & 31;
    const int j    = blockIdx.x * 8 + warp;     // h index this warp owns [0,1024)

    const int r0 = j;               // gate i row
    const int r1 = j + HDIM;        // gate f row
    const int r2 = j + 2 * HDIM;    // gate g row
    const int r3 = j + 3 * HDIM;    // gate o row

    // ---- Load recurrent weights into registers (once). Thread owns columns
    // {lane + 32k, k=0..31} of its warp's 4 gate rows: 128 regs. ----
    float wh0[32], wh1[32], wh2[32], wh3[32];
    #pragma unroll
    for (int k = 0; k < 32; k++) {
        int c = lane + 32 * k;
        wh0[k] = W_hh[(size_t)r0 * HDIM + c];
        wh1[k] = W_hh[(size_t)r1 * HDIM + c];
        wh2[k] = W_hh[(size_t)r2 * HDIM + c];
        wh3[k] = W_hh[(size_t)r3 * HDIM + c];
    }
    // ---- Input-projection weights (fused, no separate x_gates GEMM):
    // thread owns columns {lane + 32k, k=0..7} of the same 4 rows: 32 regs. ----
    float wx0[8], wx1[8], wx2[8], wx3[8];
    #pragma unroll
    for (int k = 0; k < 8; k++) {
        int c = lane + 32 * k;
        wx0[k] = W_ih[(size_t)r0 * IDIM + c];
        wx1[k] = W_ih[(size_t)r1 * IDIM + c];
        wx2[k] = W_ih[(size_t)r2 * IDIM + c];
        wx3[k] = W_ih[(size_t)r3 * IDIM + c];
    }
    const float bias0 = b_ih[r0] + b_hh[r0];
    const float bias1 = b_ih[r1] + b_hh[r1];
    const float bias2 = b_ih[r2] + b_hh[r2];
    const float bias3 = b_ih[r3] + b_hh[r3];

    float c_state = 0.0f;   // meaningful on lane 0 only

    #pragma unroll 1
    for (int t = 0; t < T_STEPS; ++t) {
        // ---- Wait until all 128 blocks have published h for this step ----
        if (tid == 0) {
            const unsigned int target = (unsigned int)NBLOCKS * (unsigned int)t;
            while (*(volatile unsigned int*)&g_count < target) { }
        }
        __syncthreads();

        // ---- Stage h_{t-1} (L2, bypass L1 for coherence) and x_t into SMEM ----
        {
            float4 hv = __ldcg(reinterpret_cast<const float4*>(g_hs + (size_t)t * HDIM) + tid);
            reinterpret_cast<float4*>(h_s)[tid] = hv;
            if (tid < IDIM / 4) {
                reinterpret_cast<float4*>(x_s)[tid] =
                    reinterpret_cast<const float4*>(seq + (size_t)t * IDIM)[tid];
            }
        }
        __syncthreads();

        // ---- Gate matvec: 4 gate rows per warp, register-resident weights ----
        float a0 = 0.0f, a1 = 0.0f, a2 = 0.0f, a3 = 0.0f;
        #pragma unroll
        for (int k = 0; k < 8; k++) {
            float xv = x_s[lane + 32 * k];
            a0 = fmaf(wx0[k], xv, a0);
            a1 = fmaf(wx1[k], xv, a1);
            a2 = fmaf(wx2[k], xv, a2);
            a3 = fmaf(wx3[k], xv, a3);
        }
        #pragma unroll
        for (int k = 0; k < 32; k++) {
            float hv = h_s[lane + 32 * k];
            a0 = fmaf(wh0[k], hv, a0);
            a1 = fmaf(wh1[k], hv, a1);
            a2 = fmaf(wh2[k], hv, a2);
            a3 = fmaf(wh3[k], hv, a3);
        }

        // ---- Warp butterfly reduce all 4 gate sums ----
        #pragma unroll
        for (int off = 16; off > 0; off >>= 1) {
            a0 += __shfl_xor_sync(0xffffffffu, a0, off);
            a1 += __shfl_xor_sync(0xffffffffu, a1, off);
            a2 += __shfl_xor_sync(0xffffffffu, a2, off);
            a3 += __shfl_xor_sync(0xffffffffu, a3, off);
        }

        // ---- LSTM cell on lane 0; publish h_t ----
        if (lane == 0) {
            float gi = a0 + bias0;
            float gf = a1 + bias1;
            float gg = a2 + bias2;
            float go = a3 + bias3;
            float i_ = sigmoidf_fast(gi);
            float f_ = sigmoidf_fast(gf);
            float g_ = tanhf(gg);
            float o_ = sigmoidf_fast(go);
            c_state = f_ * c_state + i_ * g_;
            float h_ = o_ * tanhf(c_state);
            g_hs[(size_t)(t + 1) * HDIM + j] = h_;
            __threadfence();   // make h_t visible at GPU scope before arrive
        }
        __syncthreads();        // all warps' stores + fences done
        if (tid == 0) atomicAdd(&g_count, 1u);
        // Note: the poll+__syncthreads at loop top also protects h_s/x_s reuse.
    }
}

// out[t] = sigmoid(h_t . W_out + b_out); one warp per timestep.
__global__ void __launch_bounds__(256)
out_kernel(const float* __restrict__ W_out,
           const float* __restrict__ b_out,
           float* __restrict__ out)
{
    const int warp = threadIdx.x >> 5;
    const int lane = threadIdx.x & 31;
    const int t = blockIdx.x * 8 + warp;
    if (t >= T_STEPS) return;

    const float* hrow = g_hs + (size_t)(t + 1) * HDIM;
    float acc = 0.0f;
    #pragma unroll
    for (int k = 0; k < 32; k++) {
        int c = lane + 32 * k;
        acc = fmaf(hrow[c], W_out[c], acc);
    }
    #pragma unroll
    for (int off = 16; off > 0; off >>= 1)
        acc += __shfl_xor_sync(0xffffffffu, acc, off);
    if (lane == 0)
        out[t] = 1.0f / (1.0f + __expf(-(acc + b_out[0])));
}

extern "C" void kernel_launch(void* const* d_in, const int* in_sizes, int n_in,
                              void* d_out, int out_size)
{
    const float* seq   = (const float*)d_in[0];   // [8192, 256]
    const float* W_ih  = (const float*)d_in[1];   // [4096, 256]
    const float* W_hh  = (const float*)d_in[2];   // [4096, 1024]
    const float* b_ih  = (const float*)d_in[3];   // [4096]
    const float* b_hh  = (const float*)d_in[4];   // [4096]
    const float* W_out = (const float*)d_in[5];   // [1, 1024]
    const float* b_out = (const float*)d_in[6];   // [1]
    float* out = (float*)d_out;                   // [8192, 1]

    init_kernel<<<4, 256>>>();
    lstm_kernel<<<NBLOCKS, NTHREADS>>>(seq, W_ih, W_hh, b_ih, b_hh);
    out_kernel<<<T_STEPS / 8, 256>>>(W_out, b_out, out);
}